// round 4
// baseline (speedup 1.0000x reference)
#include <cuda_runtime.h>
#include <cstdint>

#define NATOMS   4096
#define BLOCK_SZ 512
#define BOXF     44.0f
#define INV_BOX  (1.0f / 44.0f)
#define CUT2     (17.5f * 17.5f)

#define T        128                 // tile size (atoms)
#define NTILE    (NATOMS / T)        // 32
#define NPAIR    (NTILE * (NTILE + 1) / 2)   // 528
#define TPB      256                 // 2 row-slices x 128 columns

// deterministic scratch: 32 partial-force slots per atom + per-CTA energy partials
__device__ float g_fpart[NTILE * NATOMS * 3];   // [slot][atom][comp]
__device__ float g_ecta[NPAIR];

__inline__ __device__ float warp_sum(float v) {
    #pragma unroll
    for (int o = 16; o > 0; o >>= 1) v += __shfl_down_sync(0xffffffffu, v, o);
    return v;
}

__global__ __launch_bounds__(TPB)
void bmh_tile_kernel(const float* __restrict__ coords,
                     const float* __restrict__ A,
                     const float* __restrict__ C,
                     const float* __restrict__ D,
                     const float* __restrict__ RHO,
                     const float* __restrict__ SIG)
{
    // decode blockIdx -> tile pair (ti <= tj)
    int k = blockIdx.x, ti = 0, rem = NTILE;
    while (k >= rem) { k -= rem; ++ti; --rem; }
    const int tj = ti + k;
    const bool diag = (ti == tj);

    const int t    = threadIdx.x;
    const int c    = t & (T - 1);     // column within tile
    const int half = t >> 7;          // which of 2 row-slices
    const int lane = t & 31;
    const int w4   = (t >> 5) & 3;    // warp id within its half

    const int jg   = tj * T + c;      // column atom (global)
    const int locj = jg & (BLOCK_SZ - 1);
    const float wbase = ((ti >> 2) == (tj >> 2)) ? 1.0f : 2.0f;  // same 512-block?

    const float xj = __ldg(&coords[3 * jg + 0]);
    const float yj = __ldg(&coords[3 * jg + 1]);
    const float zj = __ldg(&coords[3 * jg + 2]);

    const int rowbase = ti * T;
    const size_t colb = (size_t)tj * T + c;

    // row-force partials: [row][w4*3+comp], padded to 13 words -> conflict-free
    __shared__ float frow[T][13];
    __shared__ float fcol[T][3];

    float fjx = 0.f, fjy = 0.f, fjz = 0.f, en = 0.f;

    #pragma unroll 2
    for (int s = 0; s < T / 2; ++s) {
        const int i  = 2 * s + half;
        const int ig = rowbase + i;
        const size_t off = (size_t)ig * NATOMS + colb;

        const float a  = __ldg(A   + off);
        const float cc = __ldg(C   + off);
        const float dd = __ldg(D   + off);
        const float rh = __ldg(RHO + off);
        const float sg = __ldg(SIG + off);

        const float xi = __ldg(&coords[3 * ig + 0]);
        const float yi = __ldg(&coords[3 * ig + 1]);
        const float zi = __ldg(&coords[3 * ig + 2]);

        float dx = xi - xj, dy = yi - yj, dz = zi - zj;
        dx -= rintf(dx * INV_BOX) * BOXF;
        dy -= rintf(dy * INV_BOX) * BOXF;
        dz -= rintf(dz * INV_BOX) * BOXF;
        const float r2 = fmaf(dx, dx, fmaf(dy, dy, dz * dz));

        const bool valid = (r2 < CUT2)
                        && ((ig & (BLOCK_SZ - 1)) != locj)
                        && (!diag || (i < c));          // strict i<j once per pair
        const float we = valid ? wbase : 0.0f;
        const float wf = (valid && r2 > 1.0f) ? wbase : 0.0f;

        const float r2c  = fmaxf(r2, 1.0f);
        const float dinv = rsqrtf(r2c);
        const float dij  = r2c * dinv;

        const float invrh = __fdividef(1.0f, rh);
        const float e     = __expf((sg - dij) * invrh);

        const float inv2 = dinv * dinv;
        const float inv6 = inv2 * inv2 * inv2;
        const float inv8 = inv6 * inv2;

        const float ae = a * e;
        const float pe = fmaf(dd, inv8, fmaf(-cc, inv6, ae));
        en = fmaf(we, pe, en);                           // unordered pair counted once

        // g = w * pe'(d)/d
        float g = fmaf(6.0f * cc, inv8,
                       fmaf(-8.0f * dd, inv8 * inv2,
                            -(ae * invrh) * dinv));
        g *= wf;

        const float gx = g * dx, gy = g * dy, gz = g * dz;
        fjx -= gx; fjy -= gy; fjz -= gz;                 // force on column atom j

        // force on row atom i: reduce across the 32 columns of this warp
        const float rx = warp_sum(gx);
        const float ry = warp_sum(gy);
        const float rz = warp_sum(gz);
        if (lane == 0) {
            frow[i][w4 * 3 + 0] = rx;
            frow[i][w4 * 3 + 1] = ry;
            frow[i][w4 * 3 + 2] = rz;
        }
    }
    __syncthreads();

    // merge column-force partials across the two row-slices
    if (half == 1) { fcol[c][0] = fjx; fcol[c][1] = fjy; fcol[c][2] = fjz; }
    __syncthreads();
    if (half == 0) { fjx += fcol[c][0]; fjy += fcol[c][1]; fjz += fcol[c][2]; }

    // write row partials (slot tj) and column partials (slot ti)
    if (t < T) {
        const int ig = rowbase + t;
        float rx = frow[t][0] + frow[t][3] + frow[t][6] + frow[t][9];
        float ry = frow[t][1] + frow[t][4] + frow[t][7] + frow[t][10];
        float rz = frow[t][2] + frow[t][5] + frow[t][8] + frow[t][11];
        if (diag) { rx += fjx; ry += fjy; rz += fjz; }   // row atoms == col atoms
        float* dst = g_fpart + ((size_t)tj * NATOMS + ig) * 3;
        dst[0] = rx; dst[1] = ry; dst[2] = rz;
    }
    if (!diag && half == 0) {
        float* dst = g_fpart + ((size_t)ti * NATOMS + jg) * 3;
        dst[0] = fjx; dst[1] = fjy; dst[2] = fjz;
    }

    // per-CTA energy partial (deterministic shuffle tree over 8 warps)
    en = warp_sum(en);
    __shared__ float esm[TPB / 32];
    if (lane == 0) esm[t >> 5] = en;
    __syncthreads();
    if (t < 32) {
        float v = (t < TPB / 32) ? esm[t] : 0.f;
        v = warp_sum(v);
        if (t == 0) g_ecta[blockIdx.x] = v;
    }
}

__global__ __launch_bounds__(TPB)
void bmh_reduce_kernel(float* __restrict__ out)
{
    const int tid = threadIdx.x;
    if (blockIdx.x < 48) {
        const int gid = blockIdx.x * TPB + tid;          // 0..12287
        float s = 0.f;
        #pragma unroll
        for (int p = 0; p < NTILE; ++p)
            s += g_fpart[(size_t)p * (NATOMS * 3) + gid];
        out[1 + gid] = s;
    } else {
        // energy: fixed-order double sum over 528 CTA partials
        double s = 0.0;
        for (int k2 = tid; k2 < NPAIR; k2 += TPB) s += (double)g_ecta[k2];
        __shared__ double sd[TPB];
        sd[tid] = s;
        __syncthreads();
        #pragma unroll
        for (int o = TPB / 2; o > 0; o >>= 1) {
            if (tid < o) sd[tid] += sd[tid + o];
            __syncthreads();
        }
        if (tid == 0) out[0] = (float)sd[0];
    }
}

extern "C" void kernel_launch(void* const* d_in, const int* in_sizes, int n_in,
                              void* d_out, int out_size)
{
    const float* coords = (const float*)d_in[0];
    // d_in[1] = q (computed-but-unused upstream; faithfully ignored)
    const float* A   = (const float*)d_in[2];
    const float* C   = (const float*)d_in[3];
    const float* D   = (const float*)d_in[4];
    const float* RHO = (const float*)d_in[5];
    const float* SIG = (const float*)d_in[6];
    float* out = (float*)d_out;

    bmh_tile_kernel<<<NPAIR, TPB>>>(coords, A, C, D, RHO, SIG);
    bmh_reduce_kernel<<<49, TPB>>>(out);
}

// round 6
// speedup vs baseline: 1.4324x; 1.4324x over previous
#include <cuda_runtime.h>
#include <cstdint>

#define NATOMS   4096
#define BLOCK_SZ 512
#define BOXF     44.0f
#define INV_BOX  (1.0f / 44.0f)
#define CUT2     (17.5f * 17.5f)

#define T        128                        // tile size (atoms)
#define NTILE    (NATOMS / T)               // 32
#define NPAIR    (NTILE * (NTILE + 1) / 2)  // 528
#define TPB      256                        // 8 warps; each warp covers a full 128-col row

// deterministic scratch: per-(slot,atom) force partials + per-CTA energy partials
__device__ float g_fpart[NTILE * NATOMS * 3];   // [slot][atom][xyz]
__device__ float g_ecta[NPAIR];

__inline__ __device__ float warp_sum(float v) {
    #pragma unroll
    for (int o = 16; o > 0; o >>= 1) v += __shfl_down_sync(0xffffffffu, v, o);
    return v;
}

// one pair: returns weighted g*r components, accumulates energy
__inline__ __device__ void pm(float dx, float dy, float dz,
                              float a, float c, float dd, float rh, float sg,
                              bool valid, float wbase,
                              float& en, float& gx, float& gy, float& gz)
{
    dx -= rintf(dx * INV_BOX) * BOXF;
    dy -= rintf(dy * INV_BOX) * BOXF;
    dz -= rintf(dz * INV_BOX) * BOXF;
    const float r2 = fmaf(dx, dx, fmaf(dy, dy, dz * dz));

    const bool  ok = valid && (r2 < CUT2);
    const float we = ok ? wbase : 0.0f;
    const float wf = (ok && r2 > 1.0f) ? wbase : 0.0f;

    const float r2c  = fmaxf(r2, 1.0f);
    const float dinv = rsqrtf(r2c);
    const float dij  = r2c * dinv;

    const float invrh = __fdividef(1.0f, rh);
    const float e     = __expf((sg - dij) * invrh);

    const float inv2 = dinv * dinv;
    const float inv6 = inv2 * inv2 * inv2;
    const float inv8 = inv6 * inv2;

    const float ae = a * e;
    const float pe = fmaf(dd, inv8, fmaf(-c, inv6, ae));
    en = fmaf(we, pe, en);                       // unordered pair counted once

    float g = fmaf(6.0f * c, inv8,
                   fmaf(-8.0f * dd, inv8 * inv2,
                        -(ae * invrh) * dinv));
    g *= wf;
    gx = g * dx; gy = g * dy; gz = g * dz;
}

__global__ __launch_bounds__(TPB)
void bmh_tile_kernel(const float* __restrict__ coords,
                     const float* __restrict__ A,
                     const float* __restrict__ C,
                     const float* __restrict__ D,
                     const float* __restrict__ RHO,
                     const float* __restrict__ SIG)
{
    // decode blockIdx -> tile pair (ti <= tj)
    int k = blockIdx.x, ti = 0, rem = NTILE;
    while (k >= rem) { k -= rem; ++ti; --rem; }
    const int tj   = ti + k;
    const bool diag = (ti == tj);

    const int t    = threadIdx.x;
    const int lane = t & 31;
    const int w    = t >> 5;                 // warp 0..7

    // this lane owns columns jc0..jc0+3 of tile tj
    const int jc0 = 4 * lane;
    const int jg0 = tj * T + jc0;
    const float wbase = ((ti >> 2) == (tj >> 2)) ? 1.0f : 2.0f;

    // column coords: 12 contiguous floats = 3 float4 (16B-aligned: 48B*lane)
    const float4* cf = (const float4*)(coords + 3 * (size_t)jg0);
    const float4 q0 = __ldg(cf + 0);
    const float4 q1 = __ldg(cf + 1);
    const float4 q2 = __ldg(cf + 2);
    const float xj0 = q0.x, yj0 = q0.y, zj0 = q0.z;
    const float xj1 = q0.w, yj1 = q1.x, zj1 = q1.y;
    const float xj2 = q1.z, yj2 = q1.w, zj2 = q2.x;
    const float xj3 = q2.y, yj3 = q2.z, zj3 = q2.w;
    const int loc0 = (jg0 + 0) & (BLOCK_SZ - 1);
    const int loc1 = (jg0 + 1) & (BLOCK_SZ - 1);
    const int loc2 = (jg0 + 2) & (BLOCK_SZ - 1);
    const int loc3 = (jg0 + 3) & (BLOCK_SZ - 1);

    __shared__ float frow[T][3];             // row-force results (one writer per row)
    __shared__ float fcolp[8][T * 3];        // per-warp column-force partials
    __shared__ float esm[TPB / 32];

    float f0x = 0.f, f0y = 0.f, f0z = 0.f;
    float f1x = 0.f, f1y = 0.f, f1z = 0.f;
    float f2x = 0.f, f2y = 0.f, f2z = 0.f;
    float f3x = 0.f, f3y = 0.f, f3z = 0.f;
    float en  = 0.f;

    const size_t rowstart = (size_t)(ti * T) * NATOMS + tj * T + jc0;

    #pragma unroll 2
    for (int s = 0; s < T / 8; ++s) {
        const int i  = s * 8 + w;            // row within tile (warp-exclusive)
        const int ig = ti * T + i;
        const size_t off = rowstart + (size_t)i * NATOMS;

        const float4 a4 = __ldg((const float4*)(A   + off));
        const float4 c4 = __ldg((const float4*)(C   + off));
        const float4 d4 = __ldg((const float4*)(D   + off));
        const float4 r4 = __ldg((const float4*)(RHO + off));
        const float4 s4 = __ldg((const float4*)(SIG + off));

        const float xi = __ldg(&coords[3 * ig + 0]);
        const float yi = __ldg(&coords[3 * ig + 1]);
        const float zi = __ldg(&coords[3 * ig + 2]);

        const int loci = ig & (BLOCK_SZ - 1);

        float gx, gy, gz, rx, ry, rz;

        pm(xi - xj0, yi - yj0, zi - zj0, a4.x, c4.x, d4.x, r4.x, s4.x,
           (loci != loc0) && (!diag || i < jc0 + 0), wbase, en, gx, gy, gz);
        rx = gx; ry = gy; rz = gz;
        f0x -= gx; f0y -= gy; f0z -= gz;

        pm(xi - xj1, yi - yj1, zi - zj1, a4.y, c4.y, d4.y, r4.y, s4.y,
           (loci != loc1) && (!diag || i < jc0 + 1), wbase, en, gx, gy, gz);
        rx += gx; ry += gy; rz += gz;
        f1x -= gx; f1y -= gy; f1z -= gz;

        pm(xi - xj2, yi - yj2, zi - zj2, a4.z, c4.z, d4.z, r4.z, s4.z,
           (loci != loc2) && (!diag || i < jc0 + 2), wbase, en, gx, gy, gz);
        rx += gx; ry += gy; rz += gz;
        f2x -= gx; f2y -= gy; f2z -= gz;

        pm(xi - xj3, yi - yj3, zi - zj3, a4.w, c4.w, d4.w, r4.w, s4.w,
           (loci != loc3) && (!diag || i < jc0 + 3), wbase, en, gx, gy, gz);
        rx += gx; ry += gy; rz += gz;
        f3x -= gx; f3y -= gy; f3z -= gz;

        // row force: shuffle-tree reduce across 32 lanes (128 columns)
        rx = warp_sum(rx); ry = warp_sum(ry); rz = warp_sum(rz);
        if (lane == 0) { frow[i][0] = rx; frow[i][1] = ry; frow[i][2] = rz; }
    }

    // stash per-warp column partials
    float* cp = &fcolp[w][jc0 * 3];
    cp[0] = f0x; cp[1]  = f0y; cp[2]  = f0z;
    cp[3] = f1x; cp[4]  = f1y; cp[5]  = f1z;
    cp[6] = f2x; cp[7]  = f2y; cp[8]  = f2z;
    cp[9] = f3x; cp[10] = f3y; cp[11] = f3z;

    // energy partial
    en = warp_sum(en);
    if (lane == 0) esm[w] = en;
    __syncthreads();

    if (diag) {
        if (t < T) {
            float cx = 0.f, cy = 0.f, cz = 0.f;
            #pragma unroll
            for (int ww = 0; ww < 8; ++ww) {
                cx += fcolp[ww][t * 3 + 0];
                cy += fcolp[ww][t * 3 + 1];
                cz += fcolp[ww][t * 3 + 2];
            }
            float* dst = g_fpart + ((size_t)ti * NATOMS + ti * T + t) * 3;
            dst[0] = frow[t][0] + cx;
            dst[1] = frow[t][1] + cy;
            dst[2] = frow[t][2] + cz;
        }
    } else {
        if (t < T) {
            // row atoms (tile ti) -> slot tj
            float* dst = g_fpart + ((size_t)tj * NATOMS + ti * T + t) * 3;
            dst[0] = frow[t][0]; dst[1] = frow[t][1]; dst[2] = frow[t][2];
        } else {
            const int c = t - T;   // column atoms (tile tj) -> slot ti
            float cx = 0.f, cy = 0.f, cz = 0.f;
            #pragma unroll
            for (int ww = 0; ww < 8; ++ww) {
                cx += fcolp[ww][c * 3 + 0];
                cy += fcolp[ww][c * 3 + 1];
                cz += fcolp[ww][c * 3 + 2];
            }
            float* dst = g_fpart + ((size_t)ti * NATOMS + tj * T + c) * 3;
            dst[0] = cx; dst[1] = cy; dst[2] = cz;
        }
    }

    if (t < 32) {
        float v = (t < TPB / 32) ? esm[t] : 0.f;
        v = warp_sum(v);
        if (t == 0) g_ecta[blockIdx.x] = v;
    }
}

#define RTPB 128

__global__ __launch_bounds__(RTPB)
void bmh_reduce_kernel(float* __restrict__ out)
{
    const int tid = threadIdx.x;
    if (blockIdx.x < 96) {
        const int gid = blockIdx.x * RTPB + tid;        // 0..12287 (atom*3+comp)
        float s = 0.f;
        #pragma unroll
        for (int p = 0; p < NTILE; ++p)
            s += g_fpart[(size_t)p * (NATOMS * 3) + gid];
        out[1 + gid] = s;
    } else {
        // energy: fixed-order double sum over 528 CTA partials
        double s = 0.0;
        for (int k2 = tid; k2 < NPAIR; k2 += RTPB) s += (double)g_ecta[k2];
        __shared__ double sd[RTPB];
        sd[tid] = s;
        __syncthreads();
        #pragma unroll
        for (int o = RTPB / 2; o > 0; o >>= 1) {
            if (tid < o) sd[tid] += sd[tid + o];
            __syncthreads();
        }
        if (tid == 0) out[0] = (float)sd[0];
    }
}

extern "C" void kernel_launch(void* const* d_in, const int* in_sizes, int n_in,
                              void* d_out, int out_size)
{
    const float* coords = (const float*)d_in[0];
    // d_in[1] = q (computed-but-unused upstream; faithfully ignored)
    const float* A   = (const float*)d_in[2];
    const float* C   = (const float*)d_in[3];
    const float* D   = (const float*)d_in[4];
    const float* RHO = (const float*)d_in[5];
    const float* SIG = (const float*)d_in[6];
    float* out = (float*)d_out;

    bmh_tile_kernel<<<NPAIR, TPB>>>(coords, A, C, D, RHO, SIG);
    bmh_reduce_kernel<<<97, RTPB>>>(out);
}

// round 7
// speedup vs baseline: 1.8311x; 1.2783x over previous
#include <cuda_runtime.h>
#include <cstdint>

#define NATOMS   4096
#define BLOCK_SZ 512
#define BOXF     44.0f
#define INV_BOX  (1.0f / 44.0f)
#define CUT2     (17.5f * 17.5f)

#define T        256                        // tile size (atoms)
#define NTILE    (NATOMS / T)               // 16
#define NPAIR    (NTILE * (NTILE + 1) / 2)  // 136 CTAs -> single wave on 148 SMs
#define TPB      512                        // 16 warps; each warp covers all 256 cols

// deterministic scratch: per-(slot,atom) force partials + per-CTA energy partials
__device__ float g_fpart[NTILE * NATOMS * 3];   // [slot][atom][xyz]
__device__ float g_ecta[NPAIR];

__inline__ __device__ float warp_sum(float v) {
    #pragma unroll
    for (int o = 16; o > 0; o >>= 1) v += __shfl_down_sync(0xffffffffu, v, o);
    return v;
}

// one pair: returns weighted g*r components, accumulates energy
__inline__ __device__ void pm(float dx, float dy, float dz,
                              float a, float c, float dd, float rh, float sg,
                              bool valid, float wbase,
                              float& en, float& gx, float& gy, float& gz)
{
    dx -= rintf(dx * INV_BOX) * BOXF;
    dy -= rintf(dy * INV_BOX) * BOXF;
    dz -= rintf(dz * INV_BOX) * BOXF;
    const float r2 = fmaf(dx, dx, fmaf(dy, dy, dz * dz));

    const bool  ok = valid && (r2 < CUT2);
    const float we = ok ? wbase : 0.0f;
    const float wf = (ok && r2 > 1.0f) ? wbase : 0.0f;

    const float r2c  = fmaxf(r2, 1.0f);
    const float dinv = rsqrtf(r2c);
    const float dij  = r2c * dinv;

    const float invrh = __fdividef(1.0f, rh);
    const float e     = __expf((sg - dij) * invrh);

    const float inv2 = dinv * dinv;
    const float inv6 = inv2 * inv2 * inv2;
    const float inv8 = inv6 * inv2;

    const float ae = a * e;
    const float pe = fmaf(dd, inv8, fmaf(-c, inv6, ae));
    en = fmaf(we, pe, en);                       // unordered pair counted once

    float g = fmaf(6.0f * c, inv8,
                   fmaf(-8.0f * dd, inv8 * inv2,
                        -(ae * invrh) * dinv));
    g *= wf;
    gx = g * dx; gy = g * dy; gz = g * dz;
}

__global__ __launch_bounds__(TPB)
void bmh_tile_kernel(const float* __restrict__ coords,
                     const float* __restrict__ A,
                     const float* __restrict__ C,
                     const float* __restrict__ D,
                     const float* __restrict__ RHO,
                     const float* __restrict__ SIG)
{
    // decode blockIdx -> tile pair (ti <= tj)
    int k = blockIdx.x, ti = 0, rem = NTILE;
    while (k >= rem) { k -= rem; ++ti; --rem; }
    const int tj   = ti + k;
    const bool diag = (ti == tj);

    const int t    = threadIdx.x;
    const int lane = t & 31;
    const int w    = t >> 5;                 // warp 0..15

    // this lane owns columns jc0..jc0+7 of tile tj
    const int jc0 = 8 * lane;
    const int jg0 = tj * T + jc0;
    const float wbase = ((ti >> 1) == (tj >> 1)) ? 1.0f : 2.0f;  // same 512-block?

    // column coords: 24 contiguous floats = 6 float4 (48B*8*lane -> 16B aligned)
    float xj[8], yj[8], zj[8];
    {
        const float4* cf = (const float4*)(coords + 3 * (size_t)jg0);
        float v[24];
        #pragma unroll
        for (int q = 0; q < 6; ++q) {
            const float4 f = __ldg(cf + q);
            v[4 * q + 0] = f.x; v[4 * q + 1] = f.y; v[4 * q + 2] = f.z; v[4 * q + 3] = f.w;
        }
        #pragma unroll
        for (int c = 0; c < 8; ++c) { xj[c] = v[3 * c]; yj[c] = v[3 * c + 1]; zj[c] = v[3 * c + 2]; }
    }
    const int locj0 = jg0 & (BLOCK_SZ - 1);   // locj(c) = locj0 + c (no carry: jc0 mult of 8)

    __shared__ float frow[T][3];              // row-force results (one writer per row)
    __shared__ float fcolp[16][T * 3];        // per-warp column-force partials
    __shared__ float esm[TPB / 32];

    float fjx[8], fjy[8], fjz[8];
    #pragma unroll
    for (int c = 0; c < 8; ++c) { fjx[c] = 0.f; fjy[c] = 0.f; fjz[c] = 0.f; }
    float en = 0.f;

    const size_t rowstart = (size_t)(ti * T) * NATOMS + tj * T + jc0;

    #pragma unroll 2
    for (int s = 0; s < T / 16; ++s) {
        const int i  = s * 16 + w;            // row within tile (warp-exclusive)
        const int ig = ti * T + i;
        const size_t off = rowstart + (size_t)i * NATOMS;

        // 10 x LDG.128: two quads per parameter matrix
        const float4 aA = __ldg((const float4*)(A   + off));
        const float4 aB = __ldg((const float4*)(A   + off + 4));
        const float4 cA = __ldg((const float4*)(C   + off));
        const float4 cB = __ldg((const float4*)(C   + off + 4));
        const float4 dA = __ldg((const float4*)(D   + off));
        const float4 dB = __ldg((const float4*)(D   + off + 4));
        const float4 rA = __ldg((const float4*)(RHO + off));
        const float4 rB = __ldg((const float4*)(RHO + off + 4));
        const float4 sA = __ldg((const float4*)(SIG + off));
        const float4 sB = __ldg((const float4*)(SIG + off + 4));

        const float xi = __ldg(&coords[3 * ig + 0]);
        const float yi = __ldg(&coords[3 * ig + 1]);
        const float zi = __ldg(&coords[3 * ig + 2]);
        const int loci = ig & (BLOCK_SZ - 1);

        float av[8] = {aA.x, aA.y, aA.z, aA.w, aB.x, aB.y, aB.z, aB.w};
        float cv[8] = {cA.x, cA.y, cA.z, cA.w, cB.x, cB.y, cB.z, cB.w};
        float dv[8] = {dA.x, dA.y, dA.z, dA.w, dB.x, dB.y, dB.z, dB.w};
        float rv[8] = {rA.x, rA.y, rA.z, rA.w, rB.x, rB.y, rB.z, rB.w};
        float sv[8] = {sA.x, sA.y, sA.z, sA.w, sB.x, sB.y, sB.z, sB.w};

        float rx = 0.f, ry = 0.f, rz = 0.f;
        #pragma unroll
        for (int c = 0; c < 8; ++c) {
            float gx, gy, gz;
            const bool ok = (loci != locj0 + c) && (!diag || i < jc0 + c);
            pm(xi - xj[c], yi - yj[c], zi - zj[c],
               av[c], cv[c], dv[c], rv[c], sv[c], ok, wbase, en, gx, gy, gz);
            rx += gx; ry += gy; rz += gz;
            fjx[c] -= gx; fjy[c] -= gy; fjz[c] -= gz;
        }

        // row force: shuffle-tree reduce across 32 lanes (256 columns)
        rx = warp_sum(rx); ry = warp_sum(ry); rz = warp_sum(rz);
        if (lane == 0) { frow[i][0] = rx; frow[i][1] = ry; frow[i][2] = rz; }
    }

    // stash per-warp column partials
    {
        float* cp = &fcolp[w][jc0 * 3];
        #pragma unroll
        for (int c = 0; c < 8; ++c) {
            cp[3 * c + 0] = fjx[c];
            cp[3 * c + 1] = fjy[c];
            cp[3 * c + 2] = fjz[c];
        }
    }

    // energy partial
    en = warp_sum(en);
    if (lane == 0) esm[w] = en;
    __syncthreads();

    if (t < T) {
        // row atom i=t of tile ti -> slot tj (diag merges column force too)
        float rx = frow[t][0], ry = frow[t][1], rz = frow[t][2];
        if (diag) {
            #pragma unroll
            for (int ww = 0; ww < 16; ++ww) {
                rx += fcolp[ww][t * 3 + 0];
                ry += fcolp[ww][t * 3 + 1];
                rz += fcolp[ww][t * 3 + 2];
            }
        }
        float* dst = g_fpart + ((size_t)tj * NATOMS + ti * T + t) * 3;
        dst[0] = rx; dst[1] = ry; dst[2] = rz;
    } else if (!diag) {
        // column atom c of tile tj -> slot ti
        const int c = t - T;
        float cx = 0.f, cy = 0.f, cz = 0.f;
        #pragma unroll
        for (int ww = 0; ww < 16; ++ww) {
            cx += fcolp[ww][c * 3 + 0];
            cy += fcolp[ww][c * 3 + 1];
            cz += fcolp[ww][c * 3 + 2];
        }
        float* dst = g_fpart + ((size_t)ti * NATOMS + tj * T + c) * 3;
        dst[0] = cx; dst[1] = cy; dst[2] = cz;
    }

    if (t < 32) {
        float v = (t < TPB / 32) ? esm[t] : 0.f;
        v = warp_sum(v);
        if (t == 0) g_ecta[blockIdx.x] = v;
    }
}

#define RTPB 128

__global__ __launch_bounds__(RTPB)
void bmh_reduce_kernel(float* __restrict__ out)
{
    const int tid = threadIdx.x;
    if (blockIdx.x < 96) {
        const int gid = blockIdx.x * RTPB + tid;        // 0..12287 (atom*3+comp)
        float s = 0.f;
        #pragma unroll
        for (int p = 0; p < NTILE; ++p)
            s += g_fpart[(size_t)p * (NATOMS * 3) + gid];
        out[1 + gid] = s;
    } else {
        // energy: fixed-order double sum over 136 CTA partials
        double s = 0.0;
        for (int k2 = tid; k2 < NPAIR; k2 += RTPB) s += (double)g_ecta[k2];
        __shared__ double sd[RTPB];
        sd[tid] = s;
        __syncthreads();
        #pragma unroll
        for (int o = RTPB / 2; o > 0; o >>= 1) {
            if (tid < o) sd[tid] += sd[tid + o];
            __syncthreads();
        }
        if (tid == 0) out[0] = (float)sd[0];
    }
}

extern "C" void kernel_launch(void* const* d_in, const int* in_sizes, int n_in,
                              void* d_out, int out_size)
{
    const float* coords = (const float*)d_in[0];
    // d_in[1] = q (computed-but-unused upstream; faithfully ignored)
    const float* A   = (const float*)d_in[2];
    const float* C   = (const float*)d_in[3];
    const float* D   = (const float*)d_in[4];
    const float* RHO = (const float*)d_in[5];
    const float* SIG = (const float*)d_in[6];
    float* out = (float*)d_out;

    bmh_tile_kernel<<<NPAIR, TPB>>>(coords, A, C, D, RHO, SIG);
    bmh_reduce_kernel<<<97, RTPB>>>(out);
}